// round 6
// baseline (speedup 1.0000x reference)
#include <cuda_runtime.h>
#include <cstdint>

// Problem constants
#define B_   4096
#define IN_  128
#define H_   1024
#define O_   64
#define T_   25
#define G4   (4*H_)        // 4096 gate columns (interleaved: col = 4*h + gate)
#define KC0  (O_ + H_)     // 1088  layer-0 dynamic K  [y | h1]
#define KC1  (2*H_)        // 2048  layer-1 K          [h1 | h2]

// ---------------------------------------------------------------------------
// Scratch (device globals; no allocation allowed)
// ---------------------------------------------------------------------------
__device__ float g_xs[B_*IN_];          // static input, tf32-rounded
__device__ float g_Ws[G4*IN_];          // W_ih0[:, :128], gate-interleaved rows, tf32
__device__ float g_W0[G4*KC0];          // [W_ih0[:,128:192] | W_hh0], interleaved, tf32
__device__ float g_W1[G4*KC1];          // [W_ih1 | W_hh1], interleaved, tf32
__device__ float g_Wo[O_*H_];           // W_out, tf32
__device__ float g_b0[G4];              // interleaved
__device__ float g_b1[G4];              // interleaved
__device__ float g_Gs[B_*G4];           // static gate pre-activations + b0 (interleaved)
__device__ float g_x0A[B_*KC0];         // ping-pong [y_prev | h1]  (tf32)
__device__ float g_x0B[B_*KC0];
__device__ float g_x1A[B_*KC1];         // ping-pong [h1 | h2]      (tf32)
__device__ float g_x1B[B_*KC1];
__device__ float g_c1[B_*H_];
__device__ float g_c2[B_*H_];

// ---------------------------------------------------------------------------
// Helpers
// ---------------------------------------------------------------------------
__device__ __forceinline__ float to_tf32(float x) {
    float r;
    asm("cvt.rna.tf32.f32 %0, %1;" : "=f"(r) : "f"(x));
    return r;
}
__device__ __forceinline__ float fast_exp2(float x) {
    float r; asm("ex2.approx.f32 %0, %1;" : "=f"(r) : "f"(x)); return r;
}
__device__ __forceinline__ float fast_rcp(float x) {
    float r; asm("rcp.approx.f32 %0, %1;" : "=f"(r) : "f"(x)); return r;
}
__device__ __forceinline__ float sigmoid_f(float x) {
    x = fminf(fmaxf(x, -30.f), 30.f);
    float e = fast_exp2(-x * 1.4426950408889634f);
    return fast_rcp(1.f + e);
}
__device__ __forceinline__ float tanh_f(float x) {
    x = fminf(fmaxf(x, -15.f), 15.f);
    float e = fast_exp2(2.f * x * 1.4426950408889634f);
    return 1.f - 2.f * fast_rcp(e + 1.f);
}
__device__ __forceinline__ void cp16(void* s, const void* g) {
    uint32_t sa = (uint32_t)__cvta_generic_to_shared(s);
    asm volatile("cp.async.cg.shared.global [%0], [%1], 16;\n" :: "r"(sa), "l"(g));
}

// ---------------------------------------------------------------------------
// Prep kernels
// ---------------------------------------------------------------------------
// Plain concat pack (no row permutation), tf32-rounded.
__global__ void pack_cat(const float* __restrict__ a, int lda, int wa,
                         const float* __restrict__ b, int ldb, int wb,
                         float* __restrict__ dst, int rows)
{
    int w = wa + wb;
    int n = rows * w;
    for (int i = blockIdx.x * blockDim.x + threadIdx.x; i < n;
         i += gridDim.x * blockDim.x) {
        int r = i / w, k = i - r * w;
        float v = (k < wa) ? a[r * lda + k] : b[r * ldb + (k - wa)];
        dst[i] = to_tf32(v);
    }
}

// Gate-interleaved concat pack: dst row n <- source row (n&3)*H_ + (n>>2).
__global__ void pack_gate(const float* __restrict__ a, int lda, int wa,
                          const float* __restrict__ b, int ldb, int wb,
                          float* __restrict__ dst)
{
    int w = wa + wb;
    int n = G4 * w;
    for (int i = blockIdx.x * blockDim.x + threadIdx.x; i < n;
         i += gridDim.x * blockDim.x) {
        int r = i / w, k = i - r * w;
        int p = (r & 3) * H_ + (r >> 2);
        float v = (k < wa) ? a[p * lda + k] : b[p * ldb + (k - wa)];
        dst[i] = to_tf32(v);
    }
}

__global__ void add2_gate(const float* __restrict__ a, const float* __restrict__ b,
                          float* __restrict__ d)
{
    int n = blockIdx.x * blockDim.x + threadIdx.x;
    if (n < G4) {
        int p = (n & 3) * H_ + (n >> 2);
        d[n] = a[p] + b[p];
    }
}

__global__ void zerok(float* __restrict__ p, int n)
{
    for (int i = blockIdx.x * blockDim.x + threadIdx.x; i < n;
         i += gridDim.x * blockDim.x)
        p[i] = 0.f;
}

// ---------------------------------------------------------------------------
// Big TF32 GEMM:  acc[M,N] = A[M,K] * W[N,K]^T
// BM=128, BN=128, BK=32, 3-stage cp.async pipeline, 8 warps (2 M x 4 N),
// warp tile 64x32 via mma.sync.m16n8k8.tf32.
// MODE 0: C = acc + bias          (static Gs GEMM)
// MODE 1: fused LSTM cell epilogue (gate-interleaved columns):
//         pre-act = acc + (Ci ? Ci : bias); cell update on cst;
//         h (tf32) written to hd1 [+ hd2].
// ---------------------------------------------------------------------------
#define BM 128
#define BN 128
#define BK 32
#define PAD 36
#define STAGES 3
#define AS_SZ (STAGES*BM*PAD)
#define BS_SZ (STAGES*BN*PAD)
#define SMEM_BYTES ((AS_SZ + BS_SZ) * 4)

template<int MODE>
__global__ void __launch_bounds__(256, 2)
gemm_big(int K,
         const float* __restrict__ A, int lda,
         const float* __restrict__ Bw, int ldb,
         float* __restrict__ C,                 // MODE 0
         const float* __restrict__ Ci,          // MODE 1: ld = G4 (or null)
         const float* __restrict__ bias,        // ld-less [G4] (or null)
         float* __restrict__ cst,               // MODE 1: [B_, H_]
         float* __restrict__ hd1, int ldh1,
         float* __restrict__ hd2, int ldh2)
{
    extern __shared__ float sm[];
    float* Asm = sm;
    float* Bsm = sm + AS_SZ;

    const int tid  = threadIdx.x;
    const int warp = tid >> 5;
    const int lane = tid & 31;
    const int wm = (warp & 1) * 64;
    const int wn = (warp >> 1) * 32;
    const int bm0 = blockIdx.y * BM;
    const int bn0 = blockIdx.x * BN;

    const float* Ablk = A + bm0 * lda;
    const float* Bblk = Bw + bn0 * ldb;

    float c[4][4][4];
#pragma unroll
    for (int mt = 0; mt < 4; mt++)
#pragma unroll
        for (int nt = 0; nt < 4; nt++)
#pragma unroll
            for (int r = 0; r < 4; r++) c[mt][nt][r] = 0.f;

    const int numTiles = K / BK;

    auto loadStage = [&](int st, int k0) {
#pragma unroll
        for (int i = 0; i < 4; i++) {            // A: 1024 16B chunks
            int cc = tid + i * 256;
            int r = cc >> 3, kc = (cc & 7) << 2;
            cp16(&Asm[st * (BM * PAD) + r * PAD + kc], Ablk + r * lda + k0 + kc);
        }
#pragma unroll
        for (int i = 0; i < 4; i++) {            // B: 1024 16B chunks
            int cc = tid + i * 256;
            int r = cc >> 3, kc = (cc & 7) << 2;
            cp16(&Bsm[st * (BN * PAD) + r * PAD + kc], Bblk + r * ldb + k0 + kc);
        }
    };

    // prologue: stages 0 and 1 (numTiles >= 4 for every call site)
    loadStage(0, 0);
    asm volatile("cp.async.commit_group;\n" ::);
    loadStage(1, BK);
    asm volatile("cp.async.commit_group;\n" ::);

    for (int it = 0; it < numTiles; ++it) {
        asm volatile("cp.async.wait_group 1;\n" ::);
        __syncthreads();

        int nk = it + STAGES - 1;
        if (nk < numTiles) loadStage(nk % STAGES, nk * BK);
        asm volatile("cp.async.commit_group;\n" ::);

        const float* As = Asm + (it % STAGES) * (BM * PAD);
        const float* Bs = Bsm + (it % STAGES) * (BN * PAD);

#pragma unroll
        for (int kk = 0; kk < 4; kk++) {
            const int kb = kk * 8 + (lane & 3);
            uint32_t af[4][4], bf[4][2];
#pragma unroll
            for (int mt = 0; mt < 4; mt++) {
                int m = wm + mt * 16 + (lane >> 2);
                af[mt][0] = __float_as_uint(As[m * PAD + kb]);
                af[mt][1] = __float_as_uint(As[(m + 8) * PAD + kb]);
                af[mt][2] = __float_as_uint(As[m * PAD + kb + 4]);
                af[mt][3] = __float_as_uint(As[(m + 8) * PAD + kb + 4]);
            }
#pragma unroll
            for (int nt = 0; nt < 4; nt++) {
                int n = wn + nt * 8 + (lane >> 2);
                bf[nt][0] = __float_as_uint(Bs[n * PAD + kb]);
                bf[nt][1] = __float_as_uint(Bs[n * PAD + kb + 4]);
            }
#pragma unroll
            for (int mt = 0; mt < 4; mt++)
#pragma unroll
                for (int nt = 0; nt < 4; nt++)
                    asm volatile(
                        "mma.sync.aligned.m16n8k8.row.col.f32.tf32.tf32.f32 "
                        "{%0,%1,%2,%3}, {%4,%5,%6,%7}, {%8,%9}, {%0,%1,%2,%3};\n"
                        : "+f"(c[mt][nt][0]), "+f"(c[mt][nt][1]),
                          "+f"(c[mt][nt][2]), "+f"(c[mt][nt][3])
                        : "r"(af[mt][0]), "r"(af[mt][1]),
                          "r"(af[mt][2]), "r"(af[mt][3]),
                          "r"(bf[nt][0]), "r"(bf[nt][1]));
        }
    }

    // ---- epilogue ----
#pragma unroll
    for (int mt = 0; mt < 4; mt++) {
#pragma unroll
        for (int nt = 0; nt < 4; nt++) {
            int m = bm0 + wm + mt * 16 + (lane >> 2);
            int n = bn0 + wn + nt * 8 + ((lane & 3) << 1);
            float v0 = c[mt][nt][0], v1 = c[mt][nt][1];
            float v2 = c[mt][nt][2], v3 = c[mt][nt][3];

            if (MODE == 0) {
                float bv0 = bias[n], bv1 = bias[n + 1];
                C[m * G4 + n]           = v0 + bv0;
                C[m * G4 + n + 1]       = v1 + bv1;
                C[(m + 8) * G4 + n]     = v2 + bv0;
                C[(m + 8) * G4 + n + 1] = v3 + bv1;
            } else {
                if (Ci) {
                    v0 += Ci[m * G4 + n];
                    v1 += Ci[m * G4 + n + 1];
                    v2 += Ci[(m + 8) * G4 + n];
                    v3 += Ci[(m + 8) * G4 + n + 1];
                } else {
                    v0 += bias[n];     v1 += bias[n + 1];
                    v2 += bias[n];     v3 += bias[n + 1];
                }
                // Gate exchange with lane^1 partner.
                // even lane (cols 4h,4h+1 = i,f) handles row m;
                // odd lane  (cols 4h+2,4h+3 = g,o) handles row m+8.
                float e0 = __shfl_xor_sync(0xffffffffu, v0, 1);
                float e1 = __shfl_xor_sync(0xffffffffu, v1, 1);
                float e2 = __shfl_xor_sync(0xffffffffu, v2, 1);
                float e3 = __shfl_xor_sync(0xffffffffu, v3, 1);
                int h = n >> 2;
                int row; float gi, gf, gg, go;
                if ((lane & 1) == 0) { row = m;     gi = v0; gf = v1; gg = e0; go = e1; }
                else                 { row = m + 8; gi = e2; gf = e3; gg = v2; go = v3; }

                float cold = cst[row * H_ + h];
                float I = sigmoid_f(gi), F = sigmoid_f(gf);
                float G = tanh_f(gg),    Oo = sigmoid_f(go);
                float nc = F * cold + I * G;
                float nh = to_tf32(Oo * tanh_f(nc));
                cst[row * H_ + h] = nc;
                hd1[row * ldh1 + h] = nh;
                if (hd2) hd2[row * ldh2 + h] = nh;
            }
        }
    }
}

// ---------------------------------------------------------------------------
// Output GEMM (N=64): y = h2 @ Wout^T + bout, fused scatter to d_out[:,t,:]
// and tf32 feedback into x0_next[:, 0:64].
// BM=128, BN=64, BK=32, single-buffer (small), 8 warps (4 M x 2 N).
// grid (1, 32).
// ---------------------------------------------------------------------------
__global__ void __launch_bounds__(256)
gemm_out(const float* __restrict__ A, int lda,           // h2 base (x1_next + H_)
         const float* __restrict__ Bw,                   // Wo [64 x 1024]
         const float* __restrict__ bias,
         float* __restrict__ out, float* __restrict__ x0n, int t)
{
    __shared__ float As[128][BK + 4];
    __shared__ float Bs[64][BK + 4];

    const int tid  = threadIdx.x;
    const int warp = tid >> 5;
    const int lane = tid & 31;
    const int wm = (warp & 3) * 32;
    const int wn = (warp >> 2) * 32;
    const int bm0 = blockIdx.y * 128;

    float c[2][4][4];
#pragma unroll
    for (int mt = 0; mt < 2; mt++)
#pragma unroll
        for (int nt = 0; nt < 4; nt++)
#pragma unroll
            for (int r = 0; r < 4; r++) c[mt][nt][r] = 0.f;

    const float* Ablk = A + bm0 * lda;

    for (int k0 = 0; k0 < H_; k0 += BK) {
#pragma unroll
        for (int i = 0; i < 4; i++) {
            int cc = tid + i * 256;
            int r = cc >> 3, kc = (cc & 7) << 2;
            cp16(&As[r][kc], Ablk + r * lda + k0 + kc);
        }
#pragma unroll
        for (int i = 0; i < 2; i++) {
            int cc = tid + i * 256;
            int r = cc >> 3, kc = (cc & 7) << 2;
            cp16(&Bs[r][kc], Bw + r * H_ + k0 + kc);
        }
        asm volatile("cp.async.commit_group;\n" ::);
        asm volatile("cp.async.wait_group 0;\n" ::);
        __syncthreads();

#pragma unroll
        for (int kk = 0; kk < 4; kk++) {
            const int kb = kk * 8 + (lane & 3);
            uint32_t af[2][4], bf[4][2];
#pragma unroll
            for (int mt = 0; mt < 2; mt++) {
                int m = wm + mt * 16 + (lane >> 2);
                af[mt][0] = __float_as_uint(As[m    ][kb    ]);
                af[mt][1] = __float_as_uint(As[m + 8][kb    ]);
                af[mt][2] = __float_as_uint(As[m    ][kb + 4]);
                af[mt][3] = __float_as_uint(As[m + 8][kb + 4]);
            }
#pragma unroll
            for (int nt = 0; nt < 4; nt++) {
                int n = wn + nt * 8 + (lane >> 2);
                bf[nt][0] = __float_as_uint(Bs[n][kb    ]);
                bf[nt][1] = __float_as_uint(Bs[n][kb + 4]);
            }
#pragma unroll
            for (int mt = 0; mt < 2; mt++)
#pragma unroll
                for (int nt = 0; nt < 4; nt++)
                    asm volatile(
                        "mma.sync.aligned.m16n8k8.row.col.f32.tf32.tf32.f32 "
                        "{%0,%1,%2,%3}, {%4,%5,%6,%7}, {%8,%9}, {%0,%1,%2,%3};\n"
                        : "+f"(c[mt][nt][0]), "+f"(c[mt][nt][1]),
                          "+f"(c[mt][nt][2]), "+f"(c[mt][nt][3])
                        : "r"(af[mt][0]), "r"(af[mt][1]),
                          "r"(af[mt][2]), "r"(af[mt][3]),
                          "r"(bf[nt][0]), "r"(bf[nt][1]));
        }
        __syncthreads();
    }

#pragma unroll
    for (int mt = 0; mt < 2; mt++) {
#pragma unroll
        for (int nt = 0; nt < 4; nt++) {
            int m = bm0 + wm + mt * 16 + (lane >> 2);
            int n = wn + nt * 8 + ((lane & 3) << 1);
            float bv0 = bias[n], bv1 = bias[n + 1];
            float v0 = c[mt][nt][0] + bv0;
            float v1 = c[mt][nt][1] + bv1;
            float v2 = c[mt][nt][2] + bv0;
            float v3 = c[mt][nt][3] + bv1;
            out[m * (T_ * O_) + t * O_ + n]           = v0;
            out[m * (T_ * O_) + t * O_ + n + 1]       = v1;
            out[(m + 8) * (T_ * O_) + t * O_ + n]     = v2;
            out[(m + 8) * (T_ * O_) + t * O_ + n + 1] = v3;
            x0n[m * KC0 + n]           = to_tf32(v0);
            x0n[m * KC0 + n + 1]       = to_tf32(v1);
            x0n[(m + 8) * KC0 + n]     = to_tf32(v2);
            x0n[(m + 8) * KC0 + n + 1] = to_tf32(v3);
        }
    }
}

// ---------------------------------------------------------------------------
// Launch
// ---------------------------------------------------------------------------
extern "C" void kernel_launch(void* const* d_in, const int* in_sizes, int n_in,
                              void* d_out, int out_size)
{
    (void)in_sizes; (void)n_in; (void)out_size;
    const float* sIn  = (const float*)d_in[0];
    const float* Wih0 = (const float*)d_in[1];
    const float* Whh0 = (const float*)d_in[2];
    const float* bih0 = (const float*)d_in[3];
    const float* bhh0 = (const float*)d_in[4];
    const float* Wih1 = (const float*)d_in[5];
    const float* Whh1 = (const float*)d_in[6];
    const float* bih1 = (const float*)d_in[7];
    const float* bhh1 = (const float*)d_in[8];
    const float* Wout = (const float*)d_in[9];
    const float* bout = (const float*)d_in[10];
    float* out = (float*)d_out;

    float *xs, *Ws, *W0, *W1, *Wo, *b0, *b1, *Gs, *x0A, *x0B, *x1A, *x1B, *c1, *c2;
    cudaGetSymbolAddress((void**)&xs,  g_xs);
    cudaGetSymbolAddress((void**)&Ws,  g_Ws);
    cudaGetSymbolAddress((void**)&W0,  g_W0);
    cudaGetSymbolAddress((void**)&W1,  g_W1);
    cudaGetSymbolAddress((void**)&Wo,  g_Wo);
    cudaGetSymbolAddress((void**)&b0,  g_b0);
    cudaGetSymbolAddress((void**)&b1,  g_b1);
    cudaGetSymbolAddress((void**)&Gs,  g_Gs);
    cudaGetSymbolAddress((void**)&x0A, g_x0A);
    cudaGetSymbolAddress((void**)&x0B, g_x0B);
    cudaGetSymbolAddress((void**)&x1A, g_x1A);
    cudaGetSymbolAddress((void**)&x1B, g_x1B);
    cudaGetSymbolAddress((void**)&c1,  g_c1);
    cudaGetSymbolAddress((void**)&c2,  g_c2);

    static bool attr_done = false;
    if (!attr_done) {
        cudaFuncSetAttribute(gemm_big<0>,
            cudaFuncAttributeMaxDynamicSharedMemorySize, SMEM_BYTES);
        cudaFuncSetAttribute(gemm_big<1>,
            cudaFuncAttributeMaxDynamicSharedMemorySize, SMEM_BYTES);
        attr_done = true;
    }

    const int TPB = 256;

    // ---- pack weights (tf32 + gate interleave), fold biases ----
    pack_cat<<<2048, TPB>>>(sIn, IN_, IN_, nullptr, 0, 0, xs, B_);
    pack_gate<<<2048, TPB>>>(Wih0, IN_ + O_, IN_, nullptr, 0, 0, Ws);
    pack_gate<<<4096, TPB>>>(Wih0 + IN_, IN_ + O_, O_, Whh0, H_, H_, W0);
    pack_gate<<<4096, TPB>>>(Wih1, H_, H_, Whh1, H_, H_, W1);
    pack_cat<<<256, TPB>>>(Wout, H_, H_, nullptr, 0, 0, Wo, O_);
    add2_gate<<<16, TPB>>>(bih0, bhh0, b0);
    add2_gate<<<16, TPB>>>(bih1, bhh1, b1);

    // ---- zero recurrent state (replay reset) ----
    zerok<<<2048, TPB>>>(x0A, B_ * KC0);
    zerok<<<4096, TPB>>>(x1A, B_ * KC1);
    zerok<<<2048, TPB>>>(c1, B_ * H_);
    zerok<<<2048, TPB>>>(c2, B_ * H_);

    // ---- one-time static gate contribution: Gs = static @ Ws^T + b0 ----
    dim3 grid(G4 / BN, B_ / BM);   // (32, 32)
    gemm_big<0><<<grid, 256, SMEM_BYTES>>>(IN_, xs, IN_, Ws, IN_,
                                           Gs, nullptr, b0,
                                           nullptr, nullptr, 0, nullptr, 0);

    float* x0b[2] = {x0A, x0B};
    float* x1b[2] = {x1A, x1B};
    dim3 gridOut(1, B_ / 128);     // (1, 32)

    for (int t = 0; t < T_; t++) {
        float* x0c = x0b[t & 1];
        float* x0n = x0b[(t + 1) & 1];
        float* x1c = x1b[t & 1];
        float* x1n = x1b[(t + 1) & 1];

        // layer 0: gates = [y|h1]@W0^T + Gs ; cell -> c1, h1 into x0n & x1c
        gemm_big<1><<<grid, 256, SMEM_BYTES>>>(KC0, x0c, KC0, W0, KC0,
                                               nullptr, Gs, nullptr,
                                               c1, x0n + O_, KC0, x1c, KC1);

        // layer 1: gates = [h1|h2]@W1^T + b1 ; cell -> c2, h2 into x1n second half
        gemm_big<1><<<grid, 256, SMEM_BYTES>>>(KC1, x1c, KC1, W1, KC1,
                                               nullptr, nullptr, b1,
                                               c2, x1n + H_, KC1, nullptr, 0);

        // output: y = h2 @ Wout^T + bout ; fused scatter + feedback into x0n
        gemm_out<<<gridOut, 256>>>(x1n + H_, KC1, Wo, bout, out, x0n, t);
    }
}